// round 1
// baseline (speedup 1.0000x reference)
#include <cuda_runtime.h>
#include <math.h>

#define Q_ROWS 8192
#define K_COLS 1024
#define DDIM   1024
#define EPSV   1e-6f

#define BM 128
#define BN 128
#define BK 16
#define TM 8
#define TN 8
#define NCOLTILES (K_COLS / BN)   // 8

// Scratch (device globals: no allocation allowed in kernel_launch)
__device__ float g_a[Q_ROWS];                 // ||q||^2 + 2*eps*sum(q)
__device__ float g_b[K_COLS];                 // ||p||^2 - 2*eps*sum(p) + D*eps^2
__device__ float g_Sp[NCOLTILES][Q_ROWS];     // partial sum of e
__device__ float g_Tp[NCOLTILES][Q_ROWS];     // partial sum of e*dist
__device__ float g_Mp[NCOLTILES][Q_ROWS];     // partial max of e

// ---------------------------------------------------------------------------
// Prep: one warp per row of Q (8192) then per row of P (1024).
// ---------------------------------------------------------------------------
__global__ void prep_kernel(const float* __restrict__ q, const float* __restrict__ p) {
    int warp = (blockIdx.x * blockDim.x + threadIdx.x) >> 5;
    int lane = threadIdx.x & 31;
    if (warp >= Q_ROWS + K_COLS) return;

    const float* rowptr;
    if (warp < Q_ROWS) rowptr = q + (size_t)warp * DDIM;
    else               rowptr = p + (size_t)(warp - Q_ROWS) * DDIM;

    const float4* row4 = (const float4*)rowptr;
    float sq = 0.f, sm = 0.f;
    #pragma unroll
    for (int i = 0; i < (DDIM / 4) / 32; ++i) {
        float4 v = row4[lane + i * 32];
        sq += v.x * v.x + v.y * v.y + v.z * v.z + v.w * v.w;
        sm += v.x + v.y + v.z + v.w;
    }
    #pragma unroll
    for (int o = 16; o > 0; o >>= 1) {
        sq += __shfl_down_sync(0xFFFFFFFFu, sq, o);
        sm += __shfl_down_sync(0xFFFFFFFFu, sm, o);
    }
    if (lane == 0) {
        if (warp < Q_ROWS) {
            g_a[warp] = sq + 2.f * EPSV * sm;
        } else {
            g_b[warp - Q_ROWS] = sq - 2.f * EPSV * sm + (float)DDIM * EPSV * EPSV;
        }
    }
}

// ---------------------------------------------------------------------------
// GEMM + fused epilogue. 128x128 tile, K-step 16, 256 threads, 8x8 microtile.
// Writes unnormalized e = exp(-dist) into post, and per-(coltile,row)
// partial S/T/M reductions (deterministic: no atomics).
// ---------------------------------------------------------------------------
__global__ __launch_bounds__(256) void gemm_kernel(const float* __restrict__ Q,
                                                   const float* __restrict__ P,
                                                   float* __restrict__ post) {
    __shared__ float Qs[BK][BM];
    __shared__ float Ps[BK][BN];

    const int tid = threadIdx.x;
    const int tx  = tid & 15;       // 0..15 -> columns
    const int ty  = tid >> 4;       // 0..15 -> rows
    const int bx  = blockIdx.x;     // col tile (0..7)
    const int by  = blockIdx.y;     // row tile (0..63)

    const float* Qg = Q + (size_t)(by * BM) * DDIM;
    const float* Pg = P + (size_t)(bx * BN) * DDIM;

    float acc[TM][TN];
    #pragma unroll
    for (int i = 0; i < TM; ++i)
        #pragma unroll
        for (int j = 0; j < TN; ++j) acc[i][j] = 0.f;

    const int lr0 = tid >> 2;       // 0..63 (row within tile for loads)
    const int lc0 = (tid & 3) * 4;  // float col offset (0,4,8,12)

    for (int k0 = 0; k0 < DDIM; k0 += BK) {
        #pragma unroll
        for (int h = 0; h < 2; ++h) {
            int r = lr0 + h * 64;
            float4 v = *(const float4*)(Qg + (size_t)r * DDIM + k0 + lc0);
            Qs[lc0 + 0][r] = v.x; Qs[lc0 + 1][r] = v.y;
            Qs[lc0 + 2][r] = v.z; Qs[lc0 + 3][r] = v.w;
            float4 w = *(const float4*)(Pg + (size_t)r * DDIM + k0 + lc0);
            Ps[lc0 + 0][r] = w.x; Ps[lc0 + 1][r] = w.y;
            Ps[lc0 + 2][r] = w.z; Ps[lc0 + 3][r] = w.w;
        }
        __syncthreads();

        #pragma unroll
        for (int kk = 0; kk < BK; ++kk) {
            float aq[TM], ap[TN];
            #pragma unroll
            for (int i = 0; i < TM; ++i) aq[i] = Qs[kk][ty * TM + i];
            #pragma unroll
            for (int j = 0; j < TN; ++j) ap[j] = Ps[kk][tx * TN + j];
            #pragma unroll
            for (int i = 0; i < TM; ++i)
                #pragma unroll
                for (int j = 0; j < TN; ++j)
                    acc[i][j] = fmaf(aq[i], ap[j], acc[i][j]);
        }
        __syncthreads();
    }

    // Epilogue
    const int rowb = by * BM + ty * TM;
    const int colb = bx * BN + tx * TN;

    float bv[TN];
    #pragma unroll
    for (int j = 0; j < TN; ++j) bv[j] = g_b[colb + j];

    #pragma unroll
    for (int i = 0; i < TM; ++i) {
        const int row = rowb + i;
        const float av = g_a[row];
        float S = 0.f, T = 0.f, M = 0.f;
        float e[TN];
        #pragma unroll
        for (int j = 0; j < TN; ++j) {
            float d2   = av + bv[j] - 2.f * acc[i][j];
            float dist = sqrtf(fmaxf(d2, 0.f));
            float ev   = __expf(-dist);
            e[j] = ev;
            S += ev;
            T += ev * dist;
            M = fmaxf(M, ev);
        }
        float4* o = (float4*)(post + (size_t)row * K_COLS + colb);
        o[0] = make_float4(e[0], e[1], e[2], e[3]);
        o[1] = make_float4(e[4], e[5], e[6], e[7]);

        // reduce across the 16 tx lanes (lanes [0,16) or [16,32) of the warp)
        #pragma unroll
        for (int o2 = 8; o2 > 0; o2 >>= 1) {
            S += __shfl_down_sync(0xFFFFFFFFu, S, o2, 16);
            T += __shfl_down_sync(0xFFFFFFFFu, T, o2, 16);
            M = fmaxf(M, __shfl_down_sync(0xFFFFFFFFu, M, o2, 16));
        }
        if (tx == 0) {
            g_Sp[bx][row] = S;
            g_Tp[bx][row] = T;
            g_Mp[bx][row] = M;
        }
    }
}

// ---------------------------------------------------------------------------
// Finalize: one block per row. Reduce 8 partials, scale post, write c and h.
// ---------------------------------------------------------------------------
__global__ __launch_bounds__(256) void finalize_kernel(float* __restrict__ post,
                                                       float* __restrict__ c_out,
                                                       float* __restrict__ h_out) {
    const int row = blockIdx.x;
    __shared__ float sInv;

    if (threadIdx.x == 0) {
        float S = 0.f, T = 0.f, M = 0.f;
        #pragma unroll
        for (int i = 0; i < NCOLTILES; ++i) {
            S += g_Sp[i][row];
            T += g_Tp[i][row];
            M = fmaxf(M, g_Mp[i][row]);
        }
        c_out[row] = M / S;
        h_out[row] = logf(S) + T / S;
        sInv = 1.f / S;
    }
    __syncthreads();

    const float inv = sInv;
    float4* o = (float4*)(post + (size_t)row * K_COLS);
    float4 v = o[threadIdx.x];
    v.x *= inv; v.y *= inv; v.z *= inv; v.w *= inv;
    o[threadIdx.x] = v;
}

// ---------------------------------------------------------------------------
extern "C" void kernel_launch(void* const* d_in, const int* in_sizes, int n_in,
                              void* d_out, int out_size) {
    // metadata order: class_prototypes [1024,1024], query_features [8192,1024]
    const float* p = (const float*)d_in[0];
    const float* q = (const float*)d_in[1];
    if (in_sizes[0] > in_sizes[1]) {  // defensive: larger tensor is queries
        const float* t = p; p = q; q = t;
    }

    float* post = (float*)d_out;
    float* c    = post + (size_t)Q_ROWS * K_COLS;
    float* h    = c + Q_ROWS;

    int nwarps  = Q_ROWS + K_COLS;               // 9216 warps
    int nblocks = (nwarps * 32 + 255) / 256;     // 1152 blocks
    prep_kernel<<<nblocks, 256>>>(q, p);

    dim3 grid(K_COLS / BN, Q_ROWS / BM);         // (8, 64)
    gemm_kernel<<<grid, 256>>>(q, p, post);

    finalize_kernel<<<Q_ROWS, 256>>>(post, c, h);
}

// round 3
// speedup vs baseline: 2.2650x; 2.2650x over previous
#include <cuda_runtime.h>
#include <math.h>
#include <stdint.h>

#define Q_ROWS 8192
#define K_COLS 1024
#define DDIM   1024
#define EPSV   1e-6f
#define NPART  32                 // 8 col-CTAs * 4 warp-cols

// -------- scratch (device globals; no allocation allowed) --------
__device__ float g_a[Q_ROWS];                 // ||q||^2 + 2*eps*sum(q)
__device__ float g_b[K_COLS];                 // ||p||^2 - 2*eps*sum(p) + D*eps^2
__device__ float g_Sp[NPART][Q_ROWS];
__device__ float g_Tp[NPART][Q_ROWS];
__device__ float g_Mp[NPART][Q_ROWS];

static __device__ __forceinline__ uint32_t tf32r(float x) {
    uint32_t u;
    asm("cvt.rna.tf32.f32 %0, %1;" : "=r"(u) : "f"(x));
    return u;
}

static __device__ __forceinline__ void mma_tf32(float& c0, float& c1, float& c2, float& c3,
                                                uint32_t a0, uint32_t a1, uint32_t a2, uint32_t a3,
                                                uint32_t b0, uint32_t b1) {
    asm volatile(
        "mma.sync.aligned.m16n8k8.row.col.f32.tf32.tf32.f32 "
        "{%0,%1,%2,%3}, {%4,%5,%6,%7}, {%8,%9}, {%0,%1,%2,%3};"
        : "+f"(c0), "+f"(c1), "+f"(c2), "+f"(c3)
        : "r"(a0), "r"(a1), "r"(a2), "r"(a3), "r"(b0), "r"(b1));
}

// ---------------------------------------------------------------------------
// Prep: one warp per row of Q then per row of P.
// ---------------------------------------------------------------------------
__global__ void prep_kernel(const float* __restrict__ q, const float* __restrict__ p) {
    int warp = (blockIdx.x * blockDim.x + threadIdx.x) >> 5;
    int lane = threadIdx.x & 31;
    if (warp >= Q_ROWS + K_COLS) return;

    const float* rowptr = (warp < Q_ROWS) ? q + (size_t)warp * DDIM
                                          : p + (size_t)(warp - Q_ROWS) * DDIM;
    const float4* row4 = (const float4*)rowptr;
    float sq = 0.f, sm = 0.f;
    #pragma unroll
    for (int i = 0; i < (DDIM / 4) / 32; ++i) {
        float4 v = row4[lane + i * 32];
        sq += v.x * v.x + v.y * v.y + v.z * v.z + v.w * v.w;
        sm += v.x + v.y + v.z + v.w;
    }
    #pragma unroll
    for (int o = 16; o > 0; o >>= 1) {
        sq += __shfl_down_sync(0xFFFFFFFFu, sq, o);
        sm += __shfl_down_sync(0xFFFFFFFFu, sm, o);
    }
    if (lane == 0) {
        if (warp < Q_ROWS) g_a[warp] = sq + 2.f * EPSV * sm;
        else g_b[warp - Q_ROWS] = sq - 2.f * EPSV * sm + (float)DDIM * EPSV * EPSV;
    }
}

// ---------------------------------------------------------------------------
// tf32 mma.sync GEMM + fused epilogue.
// CTA: 128x128 tile, 256 threads (8 warps, 2x4 grid), warp tile 64x32.
// BK = 32 (tf32). SMEM rows padded to 36 floats -> all fragment LDS and the
// STS.128 staging writes are bank-conflict-free.
// ---------------------------------------------------------------------------
#define LDK 36
#define TILE_BYTES (128 * LDK * 4)           // 18432
#define SM_A(s) ((s) * 2 * TILE_BYTES)
#define SM_B(s) (SM_A(s) + TILE_BYTES)
#define SMEM_BYTES (4 * TILE_BYTES)          // 73728

__global__ void __launch_bounds__(256) gemm_mma(const float* __restrict__ Q,
                                                const float* __restrict__ P,
                                                float* __restrict__ post) {
    extern __shared__ char smc[];
    uint32_t* smw = (uint32_t*)smc;

    const int tid  = threadIdx.x;
    const int wid  = tid >> 5;
    const int lane = tid & 31;
    const int wm   = wid & 1;      // warp row (0..1) -> 64-row band
    const int wn   = wid >> 1;     // warp col (0..3) -> 32-col band
    const int g    = lane >> 2;    // group id (0..7)
    const int cq   = lane & 3;     // thread in group (0..3)
    const int bx = blockIdx.x, by = blockIdx.y;

    const float* Qg = Q + (size_t)(by * 128) * DDIM;
    const float* Pg = P + (size_t)(bx * 128) * DDIM;

    // gmem load indices: idx = tid + i*256 -> row = idx>>3, quad = idx&7
    float4 fa[4], fb[4];
    #pragma unroll
    for (int i = 0; i < 4; ++i) {
        int idx = tid + i * 256, row = idx >> 3, q4 = idx & 7;
        fa[i] = *(const float4*)(Qg + (size_t)row * DDIM + q4 * 4);
        fb[i] = *(const float4*)(Pg + (size_t)row * DDIM + q4 * 4);
    }

    float C[4][4][4];  // [mfrag][nfrag][c0..c3]
    #pragma unroll
    for (int i = 0; i < 4; ++i)
        #pragma unroll
        for (int j = 0; j < 4; ++j)
            #pragma unroll
            for (int r = 0; r < 4; ++r) C[i][j][r] = 0.f;

    // store chunk 0
    #pragma unroll
    for (int i = 0; i < 4; ++i) {
        int idx = tid + i * 256, row = idx >> 3, q4 = idx & 7;
        uint32_t wo = row * LDK + q4 * 4;
        *(uint4*)(smc + SM_A(0) + wo * 4) =
            make_uint4(tf32r(fa[i].x), tf32r(fa[i].y), tf32r(fa[i].z), tf32r(fa[i].w));
        *(uint4*)(smc + SM_B(0) + wo * 4) =
            make_uint4(tf32r(fb[i].x), tf32r(fb[i].y), tf32r(fb[i].z), tf32r(fb[i].w));
    }
    __syncthreads();

    for (int c = 0; c < 32; ++c) {
        const int s = c & 1;
        if (c < 31) {  // prefetch next chunk into regs
            const int k0 = (c + 1) * 32;
            #pragma unroll
            for (int i = 0; i < 4; ++i) {
                int idx = tid + i * 256, row = idx >> 3, q4 = idx & 7;
                fa[i] = *(const float4*)(Qg + (size_t)row * DDIM + k0 + q4 * 4);
                fb[i] = *(const float4*)(Pg + (size_t)row * DDIM + k0 + q4 * 4);
            }
        }

        const uint32_t* As = (const uint32_t*)(smc + SM_A(s));
        const uint32_t* Bs = (const uint32_t*)(smc + SM_B(s));
        #pragma unroll
        for (int ks = 0; ks < 4; ++ks) {
            const int kb = ks * 8;
            uint32_t a[4][4], b[4][2];
            #pragma unroll
            for (int i = 0; i < 4; ++i) {
                int m0 = wm * 64 + i * 16 + g;
                a[i][0] = As[(m0    ) * LDK + kb + cq];
                a[i][1] = As[(m0 + 8) * LDK + kb + cq];
                a[i][2] = As[(m0    ) * LDK + kb + cq + 4];
                a[i][3] = As[(m0 + 8) * LDK + kb + cq + 4];
            }
            #pragma unroll
            for (int j = 0; j < 4; ++j) {
                int n0 = wn * 32 + j * 8 + g;
                b[j][0] = Bs[n0 * LDK + kb + cq];
                b[j][1] = Bs[n0 * LDK + kb + cq + 4];
            }
            #pragma unroll
            for (int i = 0; i < 4; ++i)
                #pragma unroll
                for (int j = 0; j < 4; ++j)
                    mma_tf32(C[i][j][0], C[i][j][1], C[i][j][2], C[i][j][3],
                             a[i][0], a[i][1], a[i][2], a[i][3], b[j][0], b[j][1]);
        }
        __syncthreads();

        if (c < 31) {
            #pragma unroll
            for (int i = 0; i < 4; ++i) {
                int idx = tid + i * 256, row = idx >> 3, q4 = idx & 7;
                uint32_t wo = row * LDK + q4 * 4;
                *(uint4*)(smc + SM_A(s ^ 1) + wo * 4) =
                    make_uint4(tf32r(fa[i].x), tf32r(fa[i].y), tf32r(fa[i].z), tf32r(fa[i].w));
                *(uint4*)(smc + SM_B(s ^ 1) + wo * 4) =
                    make_uint4(tf32r(fb[i].x), tf32r(fb[i].y), tf32r(fb[i].z), tf32r(fb[i].w));
            }
            __syncthreads();
        }
    }
    (void)smw;

    // ---------------- fused epilogue on C registers ----------------
    #pragma unroll
    for (int i = 0; i < 4; ++i) {
        #pragma unroll
        for (int half = 0; half < 2; ++half) {
            const int row = by * 128 + wm * 64 + i * 16 + half * 8 + g;
            const float av = g_a[row];
            float S = 0.f, T = 0.f, M = 0.f;
            #pragma unroll
            for (int j = 0; j < 4; ++j) {
                const int col = bx * 128 + wn * 32 + j * 8 + 2 * cq;
                float cr0 = C[i][j][half * 2];
                float cr1 = C[i][j][half * 2 + 1];
                float d20 = av + g_b[col]     - 2.f * cr0;
                float d21 = av + g_b[col + 1] - 2.f * cr1;
                float di0 = sqrtf(fmaxf(d20, 0.f));
                float di1 = sqrtf(fmaxf(d21, 0.f));
                float e0 = __expf(-di0), e1 = __expf(-di1);
                S += e0 + e1;
                T += e0 * di0 + e1 * di1;
                M = fmaxf(M, fmaxf(e0, e1));
                *(float2*)(post + (size_t)row * K_COLS + col) = make_float2(e0, e1);
            }
            // reduce across the 4 lanes of the quad (same g, cq = 0..3)
            #pragma unroll
            for (int o = 1; o < 4; o <<= 1) {
                S += __shfl_xor_sync(0xFFFFFFFFu, S, o);
                T += __shfl_xor_sync(0xFFFFFFFFu, T, o);
                M = fmaxf(M, __shfl_xor_sync(0xFFFFFFFFu, M, o));
            }
            if (cq == 0) {
                const int part = bx * 4 + wn;
                g_Sp[part][row] = S;
                g_Tp[part][row] = T;
                g_Mp[part][row] = M;
            }
        }
    }
}

// ---------------------------------------------------------------------------
// Finalize: one block per row. Reduce 32 partials, scale post, write c and h.
// ---------------------------------------------------------------------------
__global__ void __launch_bounds__(256) finalize_kernel(float* __restrict__ post,
                                                       float* __restrict__ c_out,
                                                       float* __restrict__ h_out) {
    const int row = blockIdx.x;
    __shared__ float sInv;
    if (threadIdx.x == 0) {
        float S = 0.f, T = 0.f, M = 0.f;
        #pragma unroll
        for (int i = 0; i < NPART; ++i) {
            S += g_Sp[i][row];
            T += g_Tp[i][row];
            M = fmaxf(M, g_Mp[i][row]);
        }
        c_out[row] = M / S;
        h_out[row] = logf(S) + T / S;
        sInv = 1.f / S;
    }
    __syncthreads();
    const float inv = sInv;
    float4* o = (float4*)(post + (size_t)row * K_COLS);
    float4 v = o[threadIdx.x];
    v.x *= inv; v.y *= inv; v.z *= inv; v.w *= inv;
    o[threadIdx.x] = v;
}

// ---------------------------------------------------------------------------
extern "C" void kernel_launch(void* const* d_in, const int* in_sizes, int n_in,
                              void* d_out, int out_size) {
    const float* p = (const float*)d_in[0];
    const float* q = (const float*)d_in[1];
    if (in_sizes[0] > in_sizes[1]) { const float* t = p; p = q; q = t; }

    float* post = (float*)d_out;
    float* c    = post + (size_t)Q_ROWS * K_COLS;
    float* h    = c + Q_ROWS;

    cudaFuncSetAttribute(gemm_mma, cudaFuncAttributeMaxDynamicSharedMemorySize, SMEM_BYTES);

    int nwarps  = Q_ROWS + K_COLS;
    int nblocks = (nwarps * 32 + 255) / 256;
    prep_kernel<<<nblocks, 256>>>(q, p);

    dim3 grid(K_COLS / 128, Q_ROWS / 128);  // (8, 64)
    gemm_mma<<<grid, 256, SMEM_BYTES>>>(q, p, post);

    finalize_kernel<<<Q_ROWS, 256>>>(post, c, h);
}

// round 4
// speedup vs baseline: 2.9590x; 1.3064x over previous
#include <cuda_runtime.h>
#include <math.h>
#include <stdint.h>

#define Q_ROWS 8192
#define K_COLS 1024
#define DDIM   1024
#define EPSV   1e-6f
#define NPART  32                 // 8 col-CTAs * 4 warp-cols

// -------- scratch (device globals; no allocation allowed) --------
__device__ float g_a[Q_ROWS];
__device__ float g_b[K_COLS];
__device__ float g_Sp[NPART][Q_ROWS];
__device__ float g_Tp[NPART][Q_ROWS];
__device__ float g_Mp[NPART][Q_ROWS];
__device__ uint32_t g_qt[(size_t)Q_ROWS * DDIM];   // tf32-converted Q (32 MB)
__device__ uint32_t g_pt[(size_t)K_COLS * DDIM];   // tf32-converted P (4 MB)

static __device__ __forceinline__ uint32_t tf32r(float x) {
    uint32_t u;
    asm("cvt.rna.tf32.f32 %0, %1;" : "=r"(u) : "f"(x));
    return u;
}
static __device__ __forceinline__ uint32_t smem_u32(const void* p) {
    uint32_t a;
    asm("{ .reg .u64 t; cvta.to.shared.u64 t, %1; cvt.u32.u64 %0, t; }" : "=r"(a) : "l"(p));
    return a;
}
static __device__ __forceinline__ void cp16(uint32_t sdst, const void* gsrc) {
    asm volatile("cp.async.cg.shared.global [%0], [%1], 16;" :: "r"(sdst), "l"(gsrc));
}
#define CP_COMMIT() asm volatile("cp.async.commit_group;" ::: "memory")
#define CP_WAIT1()  asm volatile("cp.async.wait_group 1;" ::: "memory")
#define CP_WAIT0()  asm volatile("cp.async.wait_group 0;" ::: "memory")

static __device__ __forceinline__ void mma_tf32(float& c0, float& c1, float& c2, float& c3,
                                                uint32_t a0, uint32_t a1, uint32_t a2, uint32_t a3,
                                                uint32_t b0, uint32_t b1) {
    asm volatile(
        "mma.sync.aligned.m16n8k8.row.col.f32.tf32.tf32.f32 "
        "{%0,%1,%2,%3}, {%4,%5,%6,%7}, {%8,%9}, {%0,%1,%2,%3};"
        : "+f"(c0), "+f"(c1), "+f"(c2), "+f"(c3)
        : "r"(a0), "r"(a1), "r"(a2), "r"(a3), "r"(b0), "r"(b1));
}

// ---------------------------------------------------------------------------
// Prep: one warp per row (Q rows then P rows). Computes a/b vectors AND writes
// the tf32-converted copies used by the GEMM's cp.async path.
// ---------------------------------------------------------------------------
__global__ void prep_kernel(const float* __restrict__ q, const float* __restrict__ p) {
    int warp = (blockIdx.x * blockDim.x + threadIdx.x) >> 5;
    int lane = threadIdx.x & 31;
    if (warp >= Q_ROWS + K_COLS) return;

    const bool isQ = warp < Q_ROWS;
    const int  r   = isQ ? warp : warp - Q_ROWS;
    const float4* row4 = (const float4*)((isQ ? q : p) + (size_t)r * DDIM);
    uint4* out4 = (uint4*)((isQ ? g_qt : g_pt) + (size_t)r * DDIM);

    float sq = 0.f, sm = 0.f;
    #pragma unroll
    for (int i = 0; i < (DDIM / 4) / 32; ++i) {
        float4 v = row4[lane + i * 32];
        sq += v.x * v.x + v.y * v.y + v.z * v.z + v.w * v.w;
        sm += v.x + v.y + v.z + v.w;
        out4[lane + i * 32] = make_uint4(tf32r(v.x), tf32r(v.y), tf32r(v.z), tf32r(v.w));
    }
    #pragma unroll
    for (int o = 16; o > 0; o >>= 1) {
        sq += __shfl_down_sync(0xFFFFFFFFu, sq, o);
        sm += __shfl_down_sync(0xFFFFFFFFu, sm, o);
    }
    if (lane == 0) {
        if (isQ) g_a[r] = sq + 2.f * EPSV * sm;
        else     g_b[r] = sq - 2.f * EPSV * sm + (float)DDIM * EPSV * EPSV;
    }
}

// ---------------------------------------------------------------------------
// tf32 mma.sync GEMM + fused epilogue, cp.async 2-stage pipeline.
// CTA 128x128, 256 threads (8 warps 2x4), warp tile 64x32, BK=32.
// SMEM rows padded to 36 floats (fragment LDS conflict-free: (4g+cq)%32).
// ---------------------------------------------------------------------------
#define LDK 36
#define STAGE_BYTES (256 * LDK * 4)          // A(128 rows) + B(128 rows) = 36864
#define SM_STAGE(s) ((s) * STAGE_BYTES)
#define SM_BOFF     (128 * LDK * 4)          // B offset within a stage
#define SMEM_BYTES  (2 * STAGE_BYTES)        // 73728

__global__ void __launch_bounds__(256, 2) gemm_mma(float* __restrict__ post) {
    extern __shared__ char smc[];
    const uint32_t sb = smem_u32(smc);

    const int tid  = threadIdx.x;
    const int wid  = tid >> 5;
    const int lane = tid & 31;
    const int wm   = wid & 1;
    const int wn   = wid >> 1;
    const int g    = lane >> 2;
    const int cq   = lane & 3;
    const int bx = blockIdx.x, by = blockIdx.y;

    const uint32_t* Qg = g_qt + (size_t)(by * 128) * DDIM;
    const uint32_t* Pg = g_pt + (size_t)(bx * 128) * DDIM;

    // cp.async mapping: 8 x 16B per thread per stage (4 for A, 4 for B)
    const int lrow = tid >> 3;        // 0..31 base row
    const int lq   = tid & 7;         // 16B chunk within 32-float row
    // issue loads of chunk c into stage s
    auto issue = [&](int c, int s) {
        const int k0 = c * 32;
        #pragma unroll
        for (int i = 0; i < 4; ++i) {
            int row = lrow + i * 32;
            uint32_t so = sb + SM_STAGE(s) + (row * LDK + lq * 4) * 4;
            cp16(so, Qg + (size_t)row * DDIM + k0 + lq * 4);
            cp16(so + SM_BOFF, Pg + (size_t)row * DDIM + k0 + lq * 4);
        }
        CP_COMMIT();
    };

    float C[4][4][4];
    #pragma unroll
    for (int i = 0; i < 4; ++i)
        #pragma unroll
        for (int j = 0; j < 4; ++j)
            #pragma unroll
            for (int r = 0; r < 4; ++r) C[i][j][r] = 0.f;

    issue(0, 0);
    issue(1, 1);

    for (int c = 0; c < 32; ++c) {
        const int s = c & 1;
        if (c + 2 < 32) CP_WAIT1(); else if (c < 31) CP_WAIT1(); else CP_WAIT0();
        __syncthreads();

        const uint32_t* As = (const uint32_t*)(smc + SM_STAGE(s));
        const uint32_t* Bs = (const uint32_t*)(smc + SM_STAGE(s) + SM_BOFF);
        #pragma unroll
        for (int ks = 0; ks < 4; ++ks) {
            const int kb = ks * 8;
            uint32_t a[4][4], b[4][2];
            #pragma unroll
            for (int i = 0; i < 4; ++i) {
                int m0 = wm * 64 + i * 16 + g;
                a[i][0] = As[(m0    ) * LDK + kb + cq];
                a[i][1] = As[(m0 + 8) * LDK + kb + cq];
                a[i][2] = As[(m0    ) * LDK + kb + cq + 4];
                a[i][3] = As[(m0 + 8) * LDK + kb + cq + 4];
            }
            #pragma unroll
            for (int j = 0; j < 4; ++j) {
                int n0 = wn * 32 + j * 8 + g;
                b[j][0] = Bs[n0 * LDK + kb + cq];
                b[j][1] = Bs[n0 * LDK + kb + cq + 4];
            }
            #pragma unroll
            for (int i = 0; i < 4; ++i)
                #pragma unroll
                for (int j = 0; j < 4; ++j)
                    mma_tf32(C[i][j][0], C[i][j][1], C[i][j][2], C[i][j][3],
                             a[i][0], a[i][1], a[i][2], a[i][3], b[j][0], b[j][1]);
        }
        __syncthreads();
        if (c + 2 < 32) issue(c + 2, s);
    }

    // ---------------- fused epilogue on C registers ----------------
    #pragma unroll
    for (int i = 0; i < 4; ++i) {
        #pragma unroll
        for (int half = 0; half < 2; ++half) {
            const int row = by * 128 + wm * 64 + i * 16 + half * 8 + g;
            const float av = g_a[row];
            float S = 0.f, T = 0.f, M = 0.f;
            #pragma unroll
            for (int j = 0; j < 4; ++j) {
                const int col = bx * 128 + wn * 32 + j * 8 + 2 * cq;
                float cr0 = C[i][j][half * 2];
                float cr1 = C[i][j][half * 2 + 1];
                float d20 = av + g_b[col]     - 2.f * cr0;
                float d21 = av + g_b[col + 1] - 2.f * cr1;
                float di0 = sqrtf(fmaxf(d20, 0.f));
                float di1 = sqrtf(fmaxf(d21, 0.f));
                float e0 = __expf(-di0), e1 = __expf(-di1);
                S += e0 + e1;
                T += e0 * di0 + e1 * di1;
                M = fmaxf(M, fmaxf(e0, e1));
                *(float2*)(post + (size_t)row * K_COLS + col) = make_float2(e0, e1);
            }
            #pragma unroll
            for (int o = 1; o < 4; o <<= 1) {
                S += __shfl_xor_sync(0xFFFFFFFFu, S, o);
                T += __shfl_xor_sync(0xFFFFFFFFu, T, o);
                M = fmaxf(M, __shfl_xor_sync(0xFFFFFFFFu, M, o));
            }
            if (cq == 0) {
                const int part = bx * 4 + wn;
                g_Sp[part][row] = S;
                g_Tp[part][row] = T;
                g_Mp[part][row] = M;
            }
        }
    }
}

// ---------------------------------------------------------------------------
// Finalize: one block per row. Reduce 32 partials, scale post, write c and h.
// ---------------------------------------------------------------------------
__global__ void __launch_bounds__(256) finalize_kernel(float* __restrict__ post,
                                                       float* __restrict__ c_out,
                                                       float* __restrict__ h_out) {
    const int row = blockIdx.x;
    __shared__ float sInv;
    if (threadIdx.x == 0) {
        float S = 0.f, T = 0.f, M = 0.f;
        #pragma unroll
        for (int i = 0; i < NPART; ++i) {
            S += g_Sp[i][row];
            T += g_Tp[i][row];
            M = fmaxf(M, g_Mp[i][row]);
        }
        c_out[row] = M / S;
        h_out[row] = logf(S) + T / S;
        sInv = 1.f / S;
    }
    __syncthreads();
    const float inv = sInv;
    float4* o = (float4*)(post + (size_t)row * K_COLS);
    float4 v = o[threadIdx.x];
    v.x *= inv; v.y *= inv; v.z *= inv; v.w *= inv;
    o[threadIdx.x] = v;
}

// ---------------------------------------------------------------------------
extern "C" void kernel_launch(void* const* d_in, const int* in_sizes, int n_in,
                              void* d_out, int out_size) {
    const float* p = (const float*)d_in[0];
    const float* q = (const float*)d_in[1];
    if (in_sizes[0] > in_sizes[1]) { const float* t = p; p = q; q = t; }

    float* post = (float*)d_out;
    float* c    = post + (size_t)Q_ROWS * K_COLS;
    float* h    = c + Q_ROWS;

    cudaFuncSetAttribute(gemm_mma, cudaFuncAttributeMaxDynamicSharedMemorySize, SMEM_BYTES);

    int nwarps  = Q_ROWS + K_COLS;
    int nblocks = (nwarps * 32 + 255) / 256;
    prep_kernel<<<nblocks, 256>>>(q, p);

    dim3 grid(K_COLS / 128, Q_ROWS / 128);  // (8, 64)
    gemm_mma<<<grid, 256, SMEM_BYTES>>>(post);

    finalize_kernel<<<Q_ROWS, 256>>>(post, c, h);
}

// round 5
// speedup vs baseline: 3.1070x; 1.0500x over previous
#include <cuda_runtime.h>
#include <math.h>
#include <stdint.h>

#define Q_ROWS 8192
#define K_COLS 1024
#define DDIM   1024
#define EPSV   1e-6f
#define NPART  32                 // 8 col-CTAs * 4 warp-cols

// -------- scratch (device globals; no allocation allowed) --------
__device__ float g_a[Q_ROWS];
__device__ float g_b[K_COLS];
__device__ float g_Sp[NPART][Q_ROWS];
__device__ float g_Tp[NPART][Q_ROWS];
__device__ float g_Mp[NPART][Q_ROWS];
__device__ uint32_t g_qt[(size_t)Q_ROWS * DDIM];   // tf32-converted Q (32 MB)
__device__ uint32_t g_pt[(size_t)K_COLS * DDIM];   // tf32-converted P (4 MB)

static __device__ __forceinline__ uint32_t tf32r(float x) {
    uint32_t u;
    asm("cvt.rna.tf32.f32 %0, %1;" : "=r"(u) : "f"(x));
    return u;
}
static __device__ __forceinline__ uint32_t smem_u32(const void* p) {
    uint32_t a;
    asm("{ .reg .u64 t; cvta.to.shared.u64 t, %1; cvt.u32.u64 %0, t; }" : "=r"(a) : "l"(p));
    return a;
}
static __device__ __forceinline__ void cp16(uint32_t sdst, const void* gsrc) {
    asm volatile("cp.async.cg.shared.global [%0], [%1], 16;" :: "r"(sdst), "l"(gsrc));
}
#define CP_COMMIT() asm volatile("cp.async.commit_group;" ::: "memory")
#define CP_WAIT1()  asm volatile("cp.async.wait_group 1;" ::: "memory")
#define CP_WAIT0()  asm volatile("cp.async.wait_group 0;" ::: "memory")

static __device__ __forceinline__ void ldsm4(uint32_t& r0, uint32_t& r1, uint32_t& r2,
                                             uint32_t& r3, uint32_t addr) {
    asm volatile("ldmatrix.sync.aligned.m8n8.x4.shared.b16 {%0,%1,%2,%3}, [%4];"
                 : "=r"(r0), "=r"(r1), "=r"(r2), "=r"(r3) : "r"(addr));
}

static __device__ __forceinline__ void mma_tf32(float& c0, float& c1, float& c2, float& c3,
                                                uint32_t a0, uint32_t a1, uint32_t a2, uint32_t a3,
                                                uint32_t b0, uint32_t b1) {
    asm volatile(
        "mma.sync.aligned.m16n8k8.row.col.f32.tf32.tf32.f32 "
        "{%0,%1,%2,%3}, {%4,%5,%6,%7}, {%8,%9}, {%0,%1,%2,%3};"
        : "+f"(c0), "+f"(c1), "+f"(c2), "+f"(c3)
        : "r"(a0), "r"(a1), "r"(a2), "r"(a3), "r"(b0), "r"(b1));
}

// ---------------------------------------------------------------------------
// Prep: one warp per row (Q rows then P rows). Computes a/b vectors AND writes
// the tf32-converted copies used by the GEMM's cp.async path.
// ---------------------------------------------------------------------------
__global__ void prep_kernel(const float* __restrict__ q, const float* __restrict__ p) {
    int warp = (blockIdx.x * blockDim.x + threadIdx.x) >> 5;
    int lane = threadIdx.x & 31;
    if (warp >= Q_ROWS + K_COLS) return;

    const bool isQ = warp < Q_ROWS;
    const int  r   = isQ ? warp : warp - Q_ROWS;
    const float4* row4 = (const float4*)((isQ ? q : p) + (size_t)r * DDIM);
    uint4* out4 = (uint4*)((isQ ? g_qt : g_pt) + (size_t)r * DDIM);

    float sq = 0.f, sm = 0.f;
    #pragma unroll
    for (int i = 0; i < (DDIM / 4) / 32; ++i) {
        float4 v = row4[lane + i * 32];
        sq += v.x * v.x + v.y * v.y + v.z * v.z + v.w * v.w;
        sm += v.x + v.y + v.z + v.w;
        out4[lane + i * 32] = make_uint4(tf32r(v.x), tf32r(v.y), tf32r(v.z), tf32r(v.w));
    }
    #pragma unroll
    for (int o = 16; o > 0; o >>= 1) {
        sq += __shfl_down_sync(0xFFFFFFFFu, sq, o);
        sm += __shfl_down_sync(0xFFFFFFFFu, sm, o);
    }
    if (lane == 0) {
        if (isQ) g_a[r] = sq + 2.f * EPSV * sm;
        else     g_b[r] = sq - 2.f * EPSV * sm + (float)DDIM * EPSV * EPSV;
    }
}

// ---------------------------------------------------------------------------
// tf32 mma.sync GEMM + fused epilogue, 3-stage cp.async pipeline, ldmatrix
// fragment loads. CTA 128x128, 8 warps (2x4), warp tile 64x32, BK=32.
// SMEM rows padded to 36 floats -> ldmatrix phases are bank-conflict-free.
// ---------------------------------------------------------------------------
#define LDK 36
#define STAGE_BYTES (256 * LDK * 4)          // A(128) + B(128) rows = 36864
#define SM_BOFF     (128 * LDK * 4)
#define NSTAGE 3
#define SMEM_BYTES  (NSTAGE * STAGE_BYTES)   // 110592

__global__ void __launch_bounds__(256, 2) gemm_mma(float* __restrict__ post) {
    extern __shared__ char smc[];
    const uint32_t sb = smem_u32(smc);

    const int tid  = threadIdx.x;
    const int wid  = tid >> 5;
    const int lane = tid & 31;
    const int wm   = wid & 1;
    const int wn   = wid >> 1;
    const int g    = lane >> 2;
    const int cq   = lane & 3;
    const int bx = blockIdx.x, by = blockIdx.y;

    const uint32_t* Qg = g_qt + (size_t)(by * 128) * DDIM;
    const uint32_t* Pg = g_pt + (size_t)(bx * 128) * DDIM;

    // cp.async mapping: 8 x 16B per thread per stage (4 for A, 4 for B)
    const int lrow = tid >> 3;
    const int lq   = tid & 7;
    auto issue = [&](int c, int s) {
        const int k0 = c * 32;
        #pragma unroll
        for (int i = 0; i < 4; ++i) {
            int row = lrow + i * 32;
            uint32_t so = sb + s * STAGE_BYTES + (row * LDK + lq * 4) * 4;
            cp16(so, Qg + (size_t)row * DDIM + k0 + lq * 4);
            cp16(so + SM_BOFF, Pg + (size_t)row * DDIM + k0 + lq * 4);
        }
        CP_COMMIT();
    };

    // ldmatrix per-lane base offsets (bytes, within a stage)
    // A tiles (per i,ks): rows m0 + (lane&15), col-block (lane>>4)*4
    const uint32_t aOff = ((wm * 64 + (lane & 15)) * LDK + (lane >> 4) * 4) * 4;
    // B tiles (per jp,ks): rows wn*32 + (lane>>4)*8 + (lane&7), col-block ((lane>>3)&1)*4
    const uint32_t bOff = (uint32_t)SM_BOFF +
        ((wn * 32 + (lane >> 4) * 8 + (lane & 7)) * LDK + ((lane >> 3) & 1) * 4) * 4;

    float C[4][4][4];
    #pragma unroll
    for (int i = 0; i < 4; ++i)
        #pragma unroll
        for (int j = 0; j < 4; ++j)
            #pragma unroll
            for (int r = 0; r < 4; ++r) C[i][j][r] = 0.f;

    issue(0, 0);
    issue(1, 1);

    for (int c = 0; c < 32; ++c) {
        const int s = c % NSTAGE;
        if (c < 31) CP_WAIT1(); else CP_WAIT0();
        __syncthreads();
        if (c + 2 < 32) issue(c + 2, (c + 2) % NSTAGE);

        const uint32_t aBase = sb + s * STAGE_BYTES + aOff;
        const uint32_t bBase = sb + s * STAGE_BYTES + bOff;
        #pragma unroll
        for (int ks = 0; ks < 4; ++ks) {
            const uint32_t kadd = ks * 32;  // 8 floats
            uint32_t a[4][4], b[4][2];
            #pragma unroll
            for (int i = 0; i < 4; ++i)
                ldsm4(a[i][0], a[i][1], a[i][2], a[i][3],
                      aBase + i * (16 * LDK * 4) + kadd);
            #pragma unroll
            for (int jp = 0; jp < 2; ++jp)
                ldsm4(b[2 * jp][0], b[2 * jp][1], b[2 * jp + 1][0], b[2 * jp + 1][1],
                      bBase + jp * (16 * LDK * 4) + kadd);
            #pragma unroll
            for (int i = 0; i < 4; ++i)
                #pragma unroll
                for (int j = 0; j < 4; ++j)
                    mma_tf32(C[i][j][0], C[i][j][1], C[i][j][2], C[i][j][3],
                             a[i][0], a[i][1], a[i][2], a[i][3], b[j][0], b[j][1]);
        }
    }

    // ---------------- fused epilogue on C registers ----------------
    #pragma unroll
    for (int i = 0; i < 4; ++i) {
        #pragma unroll
        for (int half = 0; half < 2; ++half) {
            const int row = by * 128 + wm * 64 + i * 16 + half * 8 + g;
            const float av = g_a[row];
            float S = 0.f, T = 0.f, M = 0.f;
            #pragma unroll
            for (int j = 0; j < 4; ++j) {
                const int col = bx * 128 + wn * 32 + j * 8 + 2 * cq;
                float cr0 = C[i][j][half * 2];
                float cr1 = C[i][j][half * 2 + 1];
                float d20 = av + g_b[col]     - 2.f * cr0;
                float d21 = av + g_b[col + 1] - 2.f * cr1;
                float di0 = sqrtf(fmaxf(d20, 0.f));
                float di1 = sqrtf(fmaxf(d21, 0.f));
                float e0 = __expf(-di0), e1 = __expf(-di1);
                S += e0 + e1;
                T += e0 * di0 + e1 * di1;
                M = fmaxf(M, fmaxf(e0, e1));
                *(float2*)(post + (size_t)row * K_COLS + col) = make_float2(e0, e1);
            }
            #pragma unroll
            for (int o = 1; o < 4; o <<= 1) {
                S += __shfl_xor_sync(0xFFFFFFFFu, S, o);
                T += __shfl_xor_sync(0xFFFFFFFFu, T, o);
                M = fmaxf(M, __shfl_xor_sync(0xFFFFFFFFu, M, o));
            }
            if (cq == 0) {
                const int part = bx * 4 + wn;
                g_Sp[part][row] = S;
                g_Tp[part][row] = T;
                g_Mp[part][row] = M;
            }
        }
    }
}

// ---------------------------------------------------------------------------
// Finalize: one block per row. Reduce 32 partials, scale post, write c and h.
// ---------------------------------------------------------------------------
__global__ void __launch_bounds__(256) finalize_kernel(float* __restrict__ post,
                                                       float* __restrict__ c_out,
                                                       float* __restrict__ h_out) {
    const int row = blockIdx.x;
    __shared__ float sInv;
    if (threadIdx.x == 0) {
        float S = 0.f, T = 0.f, M = 0.f;
        #pragma unroll
        for (int i = 0; i < NPART; ++i) {
            S += g_Sp[i][row];
            T += g_Tp[i][row];
            M = fmaxf(M, g_Mp[i][row]);
        }
        c_out[row] = M / S;
        h_out[row] = logf(S) + T / S;
        sInv = 1.f / S;
    }
    __syncthreads();
    const float inv = sInv;
    float4* o = (float4*)(post + (size_t)row * K_COLS);
    float4 v = o[threadIdx.x];
    v.x *= inv; v.y *= inv; v.z *= inv; v.w *= inv;
    o[threadIdx.x] = v;
}

// ---------------------------------------------------------------------------
extern "C" void kernel_launch(void* const* d_in, const int* in_sizes, int n_in,
                              void* d_out, int out_size) {
    const float* p = (const float*)d_in[0];
    const float* q = (const float*)d_in[1];
    if (in_sizes[0] > in_sizes[1]) { const float* t = p; p = q; q = t; }

    float* post = (float*)d_out;
    float* c    = post + (size_t)Q_ROWS * K_COLS;
    float* h    = c + Q_ROWS;

    cudaFuncSetAttribute(gemm_mma, cudaFuncAttributeMaxDynamicSharedMemorySize, SMEM_BYTES);

    int nwarps  = Q_ROWS + K_COLS;
    int nblocks = (nwarps * 32 + 255) / 256;
    prep_kernel<<<nblocks, 256>>>(q, p);

    dim3 grid(K_COLS / 128, Q_ROWS / 128);  // (8, 64)
    gemm_mma<<<grid, 256, SMEM_BYTES>>>(post);

    finalize_kernel<<<Q_ROWS, 256>>>(post, c, h);
}

// round 6
// speedup vs baseline: 4.6619x; 1.5005x over previous
#include <cuda_runtime.h>
#include <cuda_fp16.h>
#include <math.h>
#include <stdint.h>

#define Q_ROWS 8192
#define K_COLS 1024
#define DDIM   1024
#define EPSV   1e-6f
#define NPART  32                 // 8 col-CTAs * 4 warp-cols

// -------- scratch (device globals; no allocation allowed) --------
__device__ float g_a[Q_ROWS];
__device__ float g_b[K_COLS];
__device__ float g_Sp[NPART][Q_ROWS];
__device__ float g_Tp[NPART][Q_ROWS];
__device__ float g_Mp[NPART][Q_ROWS];
__device__ __half g_qh[(size_t)Q_ROWS * DDIM];   // fp16 Q (16 MB)
__device__ __half g_ph[(size_t)K_COLS * DDIM];   // fp16 P (2 MB)

static __device__ __forceinline__ uint32_t smem_u32(const void* p) {
    uint32_t a;
    asm("{ .reg .u64 t; cvta.to.shared.u64 t, %1; cvt.u32.u64 %0, t; }" : "=r"(a) : "l"(p));
    return a;
}
static __device__ __forceinline__ void cp16(uint32_t sdst, const void* gsrc) {
    asm volatile("cp.async.cg.shared.global [%0], [%1], 16;" :: "r"(sdst), "l"(gsrc));
}
#define CP_COMMIT() asm volatile("cp.async.commit_group;" ::: "memory")
#define CP_WAIT2()  asm volatile("cp.async.wait_group 2;" ::: "memory")
#define CP_WAIT1()  asm volatile("cp.async.wait_group 1;" ::: "memory")
#define CP_WAIT0()  asm volatile("cp.async.wait_group 0;" ::: "memory")

static __device__ __forceinline__ void ldsm4(uint32_t& r0, uint32_t& r1, uint32_t& r2,
                                             uint32_t& r3, uint32_t addr) {
    asm volatile("ldmatrix.sync.aligned.m8n8.x4.shared.b16 {%0,%1,%2,%3}, [%4];"
                 : "=r"(r0), "=r"(r1), "=r"(r2), "=r"(r3) : "r"(addr));
}
static __device__ __forceinline__ void mma_f16(float& c0, float& c1, float& c2, float& c3,
                                               uint32_t a0, uint32_t a1, uint32_t a2, uint32_t a3,
                                               uint32_t b0, uint32_t b1) {
    asm volatile(
        "mma.sync.aligned.m16n8k16.row.col.f32.f16.f16.f32 "
        "{%0,%1,%2,%3}, {%4,%5,%6,%7}, {%8,%9}, {%0,%1,%2,%3};"
        : "+f"(c0), "+f"(c1), "+f"(c2), "+f"(c3)
        : "r"(a0), "r"(a1), "r"(a2), "r"(a3), "r"(b0), "r"(b1));
}

// ---------------------------------------------------------------------------
// Prep: one warp per row (Q rows then P rows). Computes a/b vectors AND writes
// fp16 copies of Q and P for the GEMM's cp.async path.
// ---------------------------------------------------------------------------
__global__ void prep_kernel(const float* __restrict__ q, const float* __restrict__ p) {
    int warp = (blockIdx.x * blockDim.x + threadIdx.x) >> 5;
    int lane = threadIdx.x & 31;
    if (warp >= Q_ROWS + K_COLS) return;

    const bool isQ = warp < Q_ROWS;
    const int  r   = isQ ? warp : warp - Q_ROWS;
    const float4* row4 = (const float4*)((isQ ? q : p) + (size_t)r * DDIM);
    __half2* out2 = (__half2*)((isQ ? g_qh : g_ph) + (size_t)r * DDIM);

    float sq = 0.f, sm = 0.f;
    #pragma unroll
    for (int i = 0; i < (DDIM / 4) / 32; ++i) {
        float4 v = row4[lane + i * 32];
        sq += v.x * v.x + v.y * v.y + v.z * v.z + v.w * v.w;
        sm += v.x + v.y + v.z + v.w;
        out2[2 * (lane + i * 32)]     = __floats2half2_rn(v.x, v.y);
        out2[2 * (lane + i * 32) + 1] = __floats2half2_rn(v.z, v.w);
    }
    #pragma unroll
    for (int o = 16; o > 0; o >>= 1) {
        sq += __shfl_down_sync(0xFFFFFFFFu, sq, o);
        sm += __shfl_down_sync(0xFFFFFFFFu, sm, o);
    }
    if (lane == 0) {
        if (isQ) g_a[r] = sq + 2.f * EPSV * sm;
        else     g_b[r] = sq - 2.f * EPSV * sm + (float)DDIM * EPSV * EPSV;
    }
}

// ---------------------------------------------------------------------------
// fp16 mma.sync m16n8k16 GEMM + fused epilogue, 4-stage cp.async pipeline,
// ldmatrix fragment loads. CTA 128x128, 8 warps (2x4), warp tile 64x32, BK=32.
// SMEM rows padded to 40 halves -> ldmatrix phases are bank-conflict-free.
// ---------------------------------------------------------------------------
#define LDH 40
#define ROW_BYTES (LDH * 2)                  // 80
#define A_BYTES   (128 * ROW_BYTES)          // 10240
#define STAGE_BYTES (2 * A_BYTES)            // 20480
#define NSTAGE 4
#define SMEM_BYTES (NSTAGE * STAGE_BYTES)    // 81920

__global__ void __launch_bounds__(256, 2) gemm_mma(float* __restrict__ post) {
    extern __shared__ char smc[];
    const uint32_t sb = smem_u32(smc);

    const int tid  = threadIdx.x;
    const int wid  = tid >> 5;
    const int lane = tid & 31;
    const int wm   = wid & 1;
    const int wn   = wid >> 1;
    const int g    = lane >> 2;
    const int cq   = lane & 3;
    const int bx = blockIdx.x, by = blockIdx.y;

    const __half* Qg = g_qh + (size_t)(by * 128) * DDIM;
    const __half* Pg = g_ph + (size_t)(bx * 128) * DDIM;

    // cp.async: 4 x 16B per thread per stage (2 A + 2 B)
    auto issue = [&](int c, int s) {
        const int k0 = c * 32;   // halves
        #pragma unroll
        for (int i = 0; i < 2; ++i) {
            int idx = tid + i * 256, row = idx >> 2, ch = idx & 3;
            uint32_t so = sb + s * STAGE_BYTES + row * ROW_BYTES + ch * 16;
            cp16(so, Qg + (size_t)row * DDIM + k0 + ch * 8);
            cp16(so + A_BYTES, Pg + (size_t)row * DDIM + k0 + ch * 8);
        }
        CP_COMMIT();
    };

    // ldmatrix per-lane base offsets (bytes, within a stage)
    // A x4: lanes 0-15 -> rows m0+0..15 (k-off 0), lanes 16-31 -> same rows k-off 8
    const uint32_t aOff = ((wm * 64 + (lane & 15)) * LDH + (lane >> 4) * 8) * 2;
    // B x4 (two j-tiles): n-row = (l&7) [+ jtile (l>>4)*8], k-off = ((l>>3)&1)*8
    const uint32_t bOff = (uint32_t)A_BYTES +
        ((wn * 32 + (lane >> 4) * 8 + (lane & 7)) * LDH + ((lane >> 3) & 1) * 8) * 2;

    float C[4][4][4];
    #pragma unroll
    for (int i = 0; i < 4; ++i)
        #pragma unroll
        for (int j = 0; j < 4; ++j)
            #pragma unroll
            for (int r = 0; r < 4; ++r) C[i][j][r] = 0.f;

    issue(0, 0);
    issue(1, 1);
    issue(2, 2);

    for (int c = 0; c < 32; ++c) {
        const int s = c & 3;
        if (c <= 29) CP_WAIT2(); else if (c == 30) CP_WAIT1(); else CP_WAIT0();
        __syncthreads();
        if (c + 3 < 32) issue(c + 3, (c + 3) & 3);

        const uint32_t aBase = sb + s * STAGE_BYTES + aOff;
        const uint32_t bBase = sb + s * STAGE_BYTES + bOff;
        #pragma unroll
        for (int ks = 0; ks < 2; ++ks) {
            const uint32_t kadd = ks * 32;   // 16 halves = 32 bytes
            uint32_t a[4][4], b[4][2];
            #pragma unroll
            for (int i = 0; i < 4; ++i)
                ldsm4(a[i][0], a[i][1], a[i][2], a[i][3],
                      aBase + i * (16 * ROW_BYTES) + kadd);
            #pragma unroll
            for (int jp = 0; jp < 2; ++jp)
                ldsm4(b[2 * jp][0], b[2 * jp][1], b[2 * jp + 1][0], b[2 * jp + 1][1],
                      bBase + jp * (16 * ROW_BYTES) + kadd);
            #pragma unroll
            for (int i = 0; i < 4; ++i)
                #pragma unroll
                for (int j = 0; j < 4; ++j)
                    mma_f16(C[i][j][0], C[i][j][1], C[i][j][2], C[i][j][3],
                            a[i][0], a[i][1], a[i][2], a[i][3], b[j][0], b[j][1]);
        }
    }

    // ---------------- fused epilogue on C registers ----------------
    #pragma unroll
    for (int i = 0; i < 4; ++i) {
        #pragma unroll
        for (int half = 0; half < 2; ++half) {
            const int row = by * 128 + wm * 64 + i * 16 + half * 8 + g;
            const float av = g_a[row];
            float S = 0.f, T = 0.f, M = 0.f;
            #pragma unroll
            for (int j = 0; j < 4; ++j) {
                const int col = bx * 128 + wn * 32 + j * 8 + 2 * cq;
                float cr0 = C[i][j][half * 2];
                float cr1 = C[i][j][half * 2 + 1];
                float d20 = av + g_b[col]     - 2.f * cr0;
                float d21 = av + g_b[col + 1] - 2.f * cr1;
                float di0 = sqrtf(fmaxf(d20, 0.f));
                float di1 = sqrtf(fmaxf(d21, 0.f));
                float e0 = __expf(-di0), e1 = __expf(-di1);
                S += e0 + e1;
                T += e0 * di0 + e1 * di1;
                M = fmaxf(M, fmaxf(e0, e1));
                *(float2*)(post + (size_t)row * K_COLS + col) = make_float2(e0, e1);
            }
            #pragma unroll
            for (int o = 1; o < 4; o <<= 1) {
                S += __shfl_xor_sync(0xFFFFFFFFu, S, o);
                T += __shfl_xor_sync(0xFFFFFFFFu, T, o);
                M = fmaxf(M, __shfl_xor_sync(0xFFFFFFFFu, M, o));
            }
            if (cq == 0) {
                const int part = bx * 4 + wn;
                g_Sp[part][row] = S;
                g_Tp[part][row] = T;
                g_Mp[part][row] = M;
            }
        }
    }
}

// ---------------------------------------------------------------------------
// Finalize: one block per row. Reduce 32 partials, scale post, write c and h.
// ---------------------------------------------------------------------------
__global__ void __launch_bounds__(256) finalize_kernel(float* __restrict__ post,
                                                       float* __restrict__ c_out,
                                                       float* __restrict__ h_out) {
    const int row = blockIdx.x;
    __shared__ float sInv;
    if (threadIdx.x == 0) {
        float S = 0.f, T = 0.f, M = 0.f;
        #pragma unroll
        for (int i = 0; i < NPART; ++i) {
            S += g_Sp[i][row];
            T += g_Tp[i][row];
            M = fmaxf(M, g_Mp[i][row]);
        }
        c_out[row] = M / S;
        h_out[row] = logf(S) + T / S;
        sInv = 1.f / S;
    }
    __syncthreads();
    const float inv = sInv;
    float4* o = (float4*)(post + (size_t)row * K_COLS);
    float4 v = o[threadIdx.x];
    v.x *= inv; v.y *= inv; v.z *= inv; v.w *= inv;
    o[threadIdx.x] = v;
}

// ---------------------------------------------------------------------------
extern "C" void kernel_launch(void* const* d_in, const int* in_sizes, int n_in,
                              void* d_out, int out_size) {
    const float* p = (const float*)d_in[0];
    const float* q = (const float*)d_in[1];
    if (in_sizes[0] > in_sizes[1]) { const float* t = p; p = q; q = t; }

    float* post = (float*)d_out;
    float* c    = post + (size_t)Q_ROWS * K_COLS;
    float* h    = c + Q_ROWS;

    cudaFuncSetAttribute(gemm_mma, cudaFuncAttributeMaxDynamicSharedMemorySize, SMEM_BYTES);

    int nwarps  = Q_ROWS + K_COLS;
    int nblocks = (nwarps * 32 + 255) / 256;
    prep_kernel<<<nblocks, 256>>>(q, p);

    dim3 grid(K_COLS / 128, Q_ROWS / 128);  // (8, 64)
    gemm_mma<<<grid, 256, SMEM_BYTES>>>(post);

    finalize_kernel<<<Q_ROWS, 256>>>(post, c, h);
}

// round 7
// speedup vs baseline: 5.5149x; 1.1830x over previous
#include <cuda_runtime.h>
#include <cuda_fp16.h>
#include <math.h>
#include <stdint.h>

#define Q_ROWS 8192
#define K_COLS 1024
#define DDIM   1024
#define EPSV   1e-6f
#define NPART  32                 // 8 col-CTAs * 4 warp-cols

// -------- scratch (device globals; no allocation allowed) --------
__device__ float g_a[Q_ROWS];
__device__ float g_b[K_COLS];
__device__ float g_Sp[NPART][Q_ROWS];
__device__ float g_Tp[NPART][Q_ROWS];
__device__ float g_Mp[NPART][Q_ROWS];
__device__ __half g_qh[(size_t)Q_ROWS * DDIM];   // fp16 Q (16 MB)
__device__ __half g_ph[(size_t)K_COLS * DDIM];   // fp16 P (2 MB)

static __device__ __forceinline__ uint32_t smem_u32(const void* p) {
    uint32_t a;
    asm("{ .reg .u64 t; cvta.to.shared.u64 t, %1; cvt.u32.u64 %0, t; }" : "=r"(a) : "l"(p));
    return a;
}
static __device__ __forceinline__ void cp16(uint32_t sdst, const void* gsrc) {
    asm volatile("cp.async.cg.shared.global [%0], [%1], 16;" :: "r"(sdst), "l"(gsrc));
}
#define CP_COMMIT() asm volatile("cp.async.commit_group;" ::: "memory")
#define CP_WAIT1()  asm volatile("cp.async.wait_group 1;" ::: "memory")
#define CP_WAIT0()  asm volatile("cp.async.wait_group 0;" ::: "memory")

static __device__ __forceinline__ void ldsm4(uint32_t& r0, uint32_t& r1, uint32_t& r2,
                                             uint32_t& r3, uint32_t addr) {
    asm volatile("ldmatrix.sync.aligned.m8n8.x4.shared.b16 {%0,%1,%2,%3}, [%4];"
                 : "=r"(r0), "=r"(r1), "=r"(r2), "=r"(r3) : "r"(addr));
}
static __device__ __forceinline__ void mma_f16(float& c0, float& c1, float& c2, float& c3,
                                               uint32_t a0, uint32_t a1, uint32_t a2, uint32_t a3,
                                               uint32_t b0, uint32_t b1) {
    asm volatile(
        "mma.sync.aligned.m16n8k16.row.col.f32.f16.f16.f32 "
        "{%0,%1,%2,%3}, {%4,%5,%6,%7}, {%8,%9}, {%0,%1,%2,%3};"
        : "+f"(c0), "+f"(c1), "+f"(c2), "+f"(c3)
        : "r"(a0), "r"(a1), "r"(a2), "r"(a3), "r"(b0), "r"(b1));
}

// ---------------------------------------------------------------------------
// Prep: one warp per row (Q rows then P rows). Computes a/b vectors AND writes
// fp16 copies of Q and P for the GEMM's cp.async path.
// ---------------------------------------------------------------------------
__global__ void prep_kernel(const float* __restrict__ q, const float* __restrict__ p) {
    int warp = (blockIdx.x * blockDim.x + threadIdx.x) >> 5;
    int lane = threadIdx.x & 31;
    if (warp >= Q_ROWS + K_COLS) return;

    const bool isQ = warp < Q_ROWS;
    const int  r   = isQ ? warp : warp - Q_ROWS;
    const float4* row4 = (const float4*)((isQ ? q : p) + (size_t)r * DDIM);
    __half2* out2 = (__half2*)((isQ ? g_qh : g_ph) + (size_t)r * DDIM);

    float sq = 0.f, sm = 0.f;
    #pragma unroll
    for (int i = 0; i < (DDIM / 4) / 32; ++i) {
        float4 v = row4[lane + i * 32];
        sq += v.x * v.x + v.y * v.y + v.z * v.z + v.w * v.w;
        sm += v.x + v.y + v.z + v.w;
        out2[2 * (lane + i * 32)]     = __floats2half2_rn(v.x, v.y);
        out2[2 * (lane + i * 32) + 1] = __floats2half2_rn(v.z, v.w);
    }
    #pragma unroll
    for (int o = 16; o > 0; o >>= 1) {
        sq += __shfl_down_sync(0xFFFFFFFFu, sq, o);
        sm += __shfl_down_sync(0xFFFFFFFFu, sm, o);
    }
    if (lane == 0) {
        if (isQ) g_a[r] = sq + 2.f * EPSV * sm;
        else     g_b[r] = sq - 2.f * EPSV * sm + (float)DDIM * EPSV * EPSV;
    }
}

// ---------------------------------------------------------------------------
// fp16 mma.sync m16n8k16 GEMM + fused epilogue, BK=64, 3-stage cp.async.
// CTA 128x128, 8 warps (2x4), warp tile 64x32, 16 mainloop iterations.
// SMEM rows padded to 72 halves (144B = 36 words, 36%32=4 -> ldmatrix phases
// conflict-free). 2 CTAs/SM (221KB smem).
// ---------------------------------------------------------------------------
#define BKH 64
#define LDH 72
#define ROW_BYTES (LDH * 2)                  // 144
#define A_BYTES   (128 * ROW_BYTES)          // 18432
#define STAGE_BYTES (2 * A_BYTES)            // 36864
#define NSTAGE 3
#define SMEM_BYTES (NSTAGE * STAGE_BYTES)    // 110592

__global__ void __launch_bounds__(256, 2) gemm_mma(float* __restrict__ post) {
    extern __shared__ char smc[];
    const uint32_t sb = smem_u32(smc);

    const int tid  = threadIdx.x;
    const int wid  = tid >> 5;
    const int lane = tid & 31;
    const int wm   = wid & 1;
    const int wn   = wid >> 1;
    const int g    = lane >> 2;
    const int cq   = lane & 3;
    const int bx = blockIdx.x, by = blockIdx.y;

    const __half* Qg = g_qh + (size_t)(by * 128) * DDIM;
    const __half* Pg = g_ph + (size_t)(bx * 128) * DDIM;

    // cp.async: 8 x 16B per thread per stage (4 A + 4 B); rows of 64 halves
    auto issue = [&](int c, int s) {
        const int k0 = c * BKH;
        #pragma unroll
        for (int i = 0; i < 4; ++i) {
            int idx = tid + i * 256, row = idx >> 3, ch = idx & 7;
            uint32_t so = sb + s * STAGE_BYTES + row * ROW_BYTES + ch * 16;
            cp16(so, Qg + (size_t)row * DDIM + k0 + ch * 8);
            cp16(so + A_BYTES, Pg + (size_t)row * DDIM + k0 + ch * 8);
        }
        CP_COMMIT();
    };

    // ldmatrix per-lane base offsets (bytes, within a stage)
    const uint32_t aOff = ((wm * 64 + (lane & 15)) * LDH + (lane >> 4) * 8) * 2;
    const uint32_t bOff = (uint32_t)A_BYTES +
        ((wn * 32 + (lane >> 4) * 8 + (lane & 7)) * LDH + ((lane >> 3) & 1) * 8) * 2;

    float C[4][4][4];
    #pragma unroll
    for (int i = 0; i < 4; ++i)
        #pragma unroll
        for (int j = 0; j < 4; ++j)
            #pragma unroll
            for (int r = 0; r < 4; ++r) C[i][j][r] = 0.f;

    issue(0, 0);
    issue(1, 1);

    for (int c = 0; c < 16; ++c) {
        const int s = c % NSTAGE;
        if (c < 15) CP_WAIT1(); else CP_WAIT0();
        __syncthreads();
        if (c + 2 < 16) issue(c + 2, (c + 2) % NSTAGE);

        const uint32_t aBase = sb + s * STAGE_BYTES + aOff;
        const uint32_t bBase = sb + s * STAGE_BYTES + bOff;
        #pragma unroll
        for (int ks = 0; ks < 4; ++ks) {
            const uint32_t kadd = ks * 32;   // 16 halves = 32 bytes
            uint32_t a[4][4], b[4][2];
            #pragma unroll
            for (int i = 0; i < 4; ++i)
                ldsm4(a[i][0], a[i][1], a[i][2], a[i][3],
                      aBase + i * (16 * ROW_BYTES) + kadd);
            #pragma unroll
            for (int jp = 0; jp < 2; ++jp)
                ldsm4(b[2 * jp][0], b[2 * jp][1], b[2 * jp + 1][0], b[2 * jp + 1][1],
                      bBase + jp * (16 * ROW_BYTES) + kadd);
            #pragma unroll
            for (int i = 0; i < 4; ++i)
                #pragma unroll
                for (int j = 0; j < 4; ++j)
                    mma_f16(C[i][j][0], C[i][j][1], C[i][j][2], C[i][j][3],
                            a[i][0], a[i][1], a[i][2], a[i][3], b[j][0], b[j][1]);
        }
    }

    // ---------------- fused epilogue on C registers ----------------
    #pragma unroll
    for (int i = 0; i < 4; ++i) {
        #pragma unroll
        for (int half = 0; half < 2; ++half) {
            const int row = by * 128 + wm * 64 + i * 16 + half * 8 + g;
            const float av = g_a[row];
            float S = 0.f, T = 0.f, M = 0.f;
            #pragma unroll
            for (int j = 0; j < 4; ++j) {
                const int col = bx * 128 + wn * 32 + j * 8 + 2 * cq;
                float cr0 = C[i][j][half * 2];
                float cr1 = C[i][j][half * 2 + 1];
                float d20 = av + g_b[col]     - 2.f * cr0;
                float d21 = av + g_b[col + 1] - 2.f * cr1;
                float di0 = sqrtf(fmaxf(d20, 0.f));
                float di1 = sqrtf(fmaxf(d21, 0.f));
                float e0 = __expf(-di0), e1 = __expf(-di1);
                S += e0 + e1;
                T += e0 * di0 + e1 * di1;
                M = fmaxf(M, fmaxf(e0, e1));
                *(float2*)(post + (size_t)row * K_COLS + col) = make_float2(e0, e1);
            }
            #pragma unroll
            for (int o = 1; o < 4; o <<= 1) {
                S += __shfl_xor_sync(0xFFFFFFFFu, S, o);
                T += __shfl_xor_sync(0xFFFFFFFFu, T, o);
                M = fmaxf(M, __shfl_xor_sync(0xFFFFFFFFu, M, o));
            }
            if (cq == 0) {
                const int part = bx * 4 + wn;
                g_Sp[part][row] = S;
                g_Tp[part][row] = T;
                g_Mp[part][row] = M;
            }
        }
    }
}

// ---------------------------------------------------------------------------
// Finalize: one block per row. Warp 0 reduces the 32 partials in parallel,
// then all 256 threads scale the row.
// ---------------------------------------------------------------------------
__global__ void __launch_bounds__(256) finalize_kernel(float* __restrict__ post,
                                                       float* __restrict__ c_out,
                                                       float* __restrict__ h_out) {
    const int row = blockIdx.x;
    const int lane = threadIdx.x & 31;
    __shared__ float sInv;
    if (threadIdx.x < 32) {
        float S = g_Sp[lane][row];
        float T = g_Tp[lane][row];
        float M = g_Mp[lane][row];
        #pragma unroll
        for (int o = 16; o > 0; o >>= 1) {
            S += __shfl_xor_sync(0xFFFFFFFFu, S, o);
            T += __shfl_xor_sync(0xFFFFFFFFu, T, o);
            M = fmaxf(M, __shfl_xor_sync(0xFFFFFFFFu, M, o));
        }
        if (lane == 0) {
            c_out[row] = M / S;
            h_out[row] = logf(S) + T / S;
            sInv = 1.f / S;
        }
    }
    __syncthreads();
    const float inv = sInv;
    float4* o = (float4*)(post + (size_t)row * K_COLS);
    float4 v = o[threadIdx.x];
    v.x *= inv; v.y *= inv; v.z *= inv; v.w *= inv;
    o[threadIdx.x] = v;
}

// ---------------------------------------------------------------------------
extern "C" void kernel_launch(void* const* d_in, const int* in_sizes, int n_in,
                              void* d_out, int out_size) {
    const float* p = (const float*)d_in[0];
    const float* q = (const float*)d_in[1];
    if (in_sizes[0] > in_sizes[1]) { const float* t = p; p = q; q = t; }

    float* post = (float*)d_out;
    float* c    = post + (size_t)Q_ROWS * K_COLS;
    float* h    = c + Q_ROWS;

    cudaFuncSetAttribute(gemm_mma, cudaFuncAttributeMaxDynamicSharedMemorySize, SMEM_BYTES);

    int nwarps  = Q_ROWS + K_COLS;
    int nblocks = (nwarps * 32 + 255) / 256;
    prep_kernel<<<nblocks, 256>>>(q, p);

    dim3 grid(K_COLS / 128, Q_ROWS / 128);  // (8, 64)
    gemm_mma<<<grid, 256, SMEM_BYTES>>>(post);

    finalize_kernel<<<Q_ROWS, 256>>>(post, c, h);
}

// round 8
// speedup vs baseline: 5.5309x; 1.0029x over previous
#include <cuda_runtime.h>
#include <cuda_fp16.h>
#include <math.h>
#include <stdint.h>

#define Q_ROWS 8192
#define K_COLS 1024
#define DDIM   1024
#define EPSV   1e-6f
#define NPART  32                 // 8 col-CTAs * 4 warp-cols

// -------- scratch (device globals; no allocation allowed) --------
__device__ float g_a[Q_ROWS];
__device__ float g_b[K_COLS];
__device__ float g_Sp[NPART][Q_ROWS];
__device__ float g_Tp[NPART][Q_ROWS];
__device__ float g_Mp[NPART][Q_ROWS];
__device__ __half g_qh[(size_t)Q_ROWS * DDIM];   // fp16 Q (16 MB)
__device__ __half g_ph[(size_t)K_COLS * DDIM];   // fp16 P (2 MB)

static __device__ __forceinline__ uint32_t smem_u32(const void* p) {
    uint32_t a;
    asm("{ .reg .u64 t; cvta.to.shared.u64 t, %1; cvt.u32.u64 %0, t; }" : "=r"(a) : "l"(p));
    return a;
}
static __device__ __forceinline__ void cp16(uint32_t sdst, const void* gsrc) {
    asm volatile("cp.async.cg.shared.global [%0], [%1], 16;" :: "r"(sdst), "l"(gsrc));
}
#define CP_COMMIT() asm volatile("cp.async.commit_group;" ::: "memory")
#define CP_WAIT1()  asm volatile("cp.async.wait_group 1;" ::: "memory")
#define CP_WAIT0()  asm volatile("cp.async.wait_group 0;" ::: "memory")

static __device__ __forceinline__ void ldsm4(uint32_t& r0, uint32_t& r1, uint32_t& r2,
                                             uint32_t& r3, uint32_t addr) {
    asm volatile("ldmatrix.sync.aligned.m8n8.x4.shared.b16 {%0,%1,%2,%3}, [%4];"
                 : "=r"(r0), "=r"(r1), "=r"(r2), "=r"(r3) : "r"(addr));
}
static __device__ __forceinline__ void mma_f16(float& c0, float& c1, float& c2, float& c3,
                                               uint32_t a0, uint32_t a1, uint32_t a2, uint32_t a3,
                                               uint32_t b0, uint32_t b1) {
    asm volatile(
        "mma.sync.aligned.m16n8k16.row.col.f32.f16.f16.f32 "
        "{%0,%1,%2,%3}, {%4,%5,%6,%7}, {%8,%9}, {%0,%1,%2,%3};"
        : "+f"(c0), "+f"(c1), "+f"(c2), "+f"(c3)
        : "r"(a0), "r"(a1), "r"(a2), "r"(a3), "r"(b0), "r"(b1));
}

// ---------------------------------------------------------------------------
// Prep: one warp per row. Computes a/b vectors, writes fp16 copies with
// fully vectorized 16B stores.
// ---------------------------------------------------------------------------
__global__ void prep_kernel(const float* __restrict__ q, const float* __restrict__ p) {
    int warp = (blockIdx.x * blockDim.x + threadIdx.x) >> 5;
    int lane = threadIdx.x & 31;
    if (warp >= Q_ROWS + K_COLS) return;

    const bool isQ = warp < Q_ROWS;
    const int  r   = isQ ? warp : warp - Q_ROWS;
    const float4* row4 = (const float4*)((isQ ? q : p) + (size_t)r * DDIM);
    uint4* out4 = (uint4*)((isQ ? g_qh : g_ph) + (size_t)r * DDIM);  // 8 halves per uint4

    float sq = 0.f, sm = 0.f;
    #pragma unroll
    for (int i = 0; i < (DDIM / 8) / 32; ++i) {   // 4 iterations, 8 floats each
        float4 v0 = row4[2 * (lane + i * 32)];
        float4 v1 = row4[2 * (lane + i * 32) + 1];
        sq += v0.x * v0.x + v0.y * v0.y + v0.z * v0.z + v0.w * v0.w;
        sq += v1.x * v1.x + v1.y * v1.y + v1.z * v1.z + v1.w * v1.w;
        sm += v0.x + v0.y + v0.z + v0.w + v1.x + v1.y + v1.z + v1.w;
        __half2 h0 = __floats2half2_rn(v0.x, v0.y);
        __half2 h1 = __floats2half2_rn(v0.z, v0.w);
        __half2 h2 = __floats2half2_rn(v1.x, v1.y);
        __half2 h3 = __floats2half2_rn(v1.z, v1.w);
        uint4 u;
        u.x = *(uint32_t*)&h0; u.y = *(uint32_t*)&h1;
        u.z = *(uint32_t*)&h2; u.w = *(uint32_t*)&h3;
        out4[lane + i * 32] = u;
    }
    #pragma unroll
    for (int o = 16; o > 0; o >>= 1) {
        sq += __shfl_down_sync(0xFFFFFFFFu, sq, o);
        sm += __shfl_down_sync(0xFFFFFFFFu, sm, o);
    }
    if (lane == 0) {
        if (isQ) g_a[r] = sq + 2.f * EPSV * sm;
        else     g_b[r] = sq - 2.f * EPSV * sm + (float)DDIM * EPSV * EPSV;
    }
}

// ---------------------------------------------------------------------------
// fp16 mma.sync m16n8k16 GEMM + fused epilogue, BK=64, 3-stage cp.async.
// CTA 128x128, 8 warps (2x4), warp tile 64x32, 16 mainloop iterations.
// SMEM rows padded to 72 halves. 2 CTAs/SM.
// ---------------------------------------------------------------------------
#define BKH 64
#define LDH 72
#define ROW_BYTES (LDH * 2)                  // 144
#define A_BYTES   (128 * ROW_BYTES)          // 18432
#define STAGE_BYTES (2 * A_BYTES)            // 36864
#define NSTAGE 3
#define SMEM_BYTES (NSTAGE * STAGE_BYTES)    // 110592

__global__ void __launch_bounds__(256, 2) gemm_mma(float* __restrict__ post) {
    extern __shared__ char smc[];
    const uint32_t sb = smem_u32(smc);

    const int tid  = threadIdx.x;
    const int wid  = tid >> 5;
    const int lane = tid & 31;
    const int wm   = wid & 1;
    const int wn   = wid >> 1;
    const int g    = lane >> 2;
    const int cq   = lane & 3;
    const int bx = blockIdx.x, by = blockIdx.y;

    const __half* Qg = g_qh + (size_t)(by * 128) * DDIM;
    const __half* Pg = g_ph + (size_t)(bx * 128) * DDIM;

    auto issue = [&](int c, int s) {
        const int k0 = c * BKH;
        #pragma unroll
        for (int i = 0; i < 4; ++i) {
            int idx = tid + i * 256, row = idx >> 3, ch = idx & 7;
            uint32_t so = sb + s * STAGE_BYTES + row * ROW_BYTES + ch * 16;
            cp16(so, Qg + (size_t)row * DDIM + k0 + ch * 8);
            cp16(so + A_BYTES, Pg + (size_t)row * DDIM + k0 + ch * 8);
        }
        CP_COMMIT();
    };

    const uint32_t aOff = ((wm * 64 + (lane & 15)) * LDH + (lane >> 4) * 8) * 2;
    const uint32_t bOff = (uint32_t)A_BYTES +
        ((wn * 32 + (lane >> 4) * 8 + (lane & 7)) * LDH + ((lane >> 3) & 1) * 8) * 2;

    float C[4][4][4];
    #pragma unroll
    for (int i = 0; i < 4; ++i)
        #pragma unroll
        for (int j = 0; j < 4; ++j)
            #pragma unroll
            for (int r = 0; r < 4; ++r) C[i][j][r] = 0.f;

    issue(0, 0);
    issue(1, 1);

    for (int c = 0; c < 16; ++c) {
        const int s = c % NSTAGE;
        if (c < 15) CP_WAIT1(); else CP_WAIT0();
        __syncthreads();
        if (c + 2 < 16) issue(c + 2, (c + 2) % NSTAGE);

        const uint32_t aBase = sb + s * STAGE_BYTES + aOff;
        const uint32_t bBase = sb + s * STAGE_BYTES + bOff;
        #pragma unroll
        for (int ks = 0; ks < 4; ++ks) {
            const uint32_t kadd = ks * 32;
            uint32_t a[4][4], b[4][2];
            #pragma unroll
            for (int i = 0; i < 4; ++i)
                ldsm4(a[i][0], a[i][1], a[i][2], a[i][3],
                      aBase + i * (16 * ROW_BYTES) + kadd);
            #pragma unroll
            for (int jp = 0; jp < 2; ++jp)
                ldsm4(b[2 * jp][0], b[2 * jp][1], b[2 * jp + 1][0], b[2 * jp + 1][1],
                      bBase + jp * (16 * ROW_BYTES) + kadd);
            #pragma unroll
            for (int i = 0; i < 4; ++i)
                #pragma unroll
                for (int j = 0; j < 4; ++j)
                    mma_f16(C[i][j][0], C[i][j][1], C[i][j][2], C[i][j][3],
                            a[i][0], a[i][1], a[i][2], a[i][3], b[j][0], b[j][1]);
        }
    }

    // ---------------- fused epilogue on C registers ----------------
    #pragma unroll
    for (int i = 0; i < 4; ++i) {
        #pragma unroll
        for (int half = 0; half < 2; ++half) {
            const int row = by * 128 + wm * 64 + i * 16 + half * 8 + g;
            const float av = g_a[row];
            float S = 0.f, T = 0.f, M = 0.f;
            #pragma unroll
            for (int j = 0; j < 4; ++j) {
                const int col = bx * 128 + wn * 32 + j * 8 + 2 * cq;
                float cr0 = C[i][j][half * 2];
                float cr1 = C[i][j][half * 2 + 1];
                float d20 = av + g_b[col]     - 2.f * cr0;
                float d21 = av + g_b[col + 1] - 2.f * cr1;
                float di0 = sqrtf(fmaxf(d20, 0.f));
                float di1 = sqrtf(fmaxf(d21, 0.f));
                float e0 = __expf(-di0), e1 = __expf(-di1);
                S += e0 + e1;
                T += e0 * di0 + e1 * di1;
                M = fmaxf(M, fmaxf(e0, e1));
                *(float2*)(post + (size_t)row * K_COLS + col) = make_float2(e0, e1);
            }
            #pragma unroll
            for (int o = 1; o < 4; o <<= 1) {
                S += __shfl_xor_sync(0xFFFFFFFFu, S, o);
                T += __shfl_xor_sync(0xFFFFFFFFu, T, o);
                M = fmaxf(M, __shfl_xor_sync(0xFFFFFFFFu, M, o));
            }
            if (cq == 0) {
                const int part = bx * 4 + wn;
                g_Sp[part][row] = S;
                g_Tp[part][row] = T;
                g_Mp[part][row] = M;
            }
        }
    }
}

// ---------------------------------------------------------------------------
// Finalize: one block per row. The row load is issued FIRST so its DRAM
// latency overlaps warp 0's partial reduction.
// ---------------------------------------------------------------------------
__global__ void __launch_bounds__(256) finalize_kernel(float* __restrict__ post,
                                                       float* __restrict__ c_out,
                                                       float* __restrict__ h_out) {
    const int row = blockIdx.x;
    const int lane = threadIdx.x & 31;
    __shared__ float sInv;

    // issue row load early (overlaps the reduction below)
    float4* o = (float4*)(post + (size_t)row * K_COLS);
    float4 v = o[threadIdx.x];

    if (threadIdx.x < 32) {
        float S = g_Sp[lane][row];
        float T = g_Tp[lane][row];
        float M = g_Mp[lane][row];
        #pragma unroll
        for (int of = 16; of > 0; of >>= 1) {
            S += __shfl_xor_sync(0xFFFFFFFFu, S, of);
            T += __shfl_xor_sync(0xFFFFFFFFu, T, of);
            M = fmaxf(M, __shfl_xor_sync(0xFFFFFFFFu, M, of));
        }
        if (lane == 0) {
            c_out[row] = M / S;
            h_out[row] = logf(S) + T / S;
            sInv = 1.f / S;
        }
    }
    __syncthreads();
    const float inv = sInv;
    v.x *= inv; v.y *= inv; v.z *= inv; v.w *= inv;
    o[threadIdx.x] = v;
}

// ---------------------------------------------------------------------------
extern "C" void kernel_launch(void* const* d_in, const int* in_sizes, int n_in,
                              void* d_out, int out_size) {
    const float* p = (const float*)d_in[0];
    const float* q = (const float*)d_in[1];
    if (in_sizes[0] > in_sizes[1]) { const float* t = p; p = q; q = t; }

    float* post = (float*)d_out;
    float* c    = post + (size_t)Q_ROWS * K_COLS;
    float* h    = c + Q_ROWS;

    cudaFuncSetAttribute(gemm_mma, cudaFuncAttributeMaxDynamicSharedMemorySize, SMEM_BYTES);

    int nwarps  = Q_ROWS + K_COLS;
    int nblocks = (nwarps * 32 + 255) / 256;
    prep_kernel<<<nblocks, 256>>>(q, p);

    dim3 grid(K_COLS / 128, Q_ROWS / 128);  // (8, 64)
    gemm_mma<<<grid, 256, SMEM_BYTES>>>(post);

    finalize_kernel<<<Q_ROWS, 256>>>(post, c, h);
}